// round 2
// baseline (speedup 1.0000x reference)
#include <cuda_runtime.h>
#include <cuda_bf16.h>
#include <math.h>

#define N_USER   100000
#define N_ITEM   50000
#define NTOT     150000
#define EMB      64
#define FEAT     384
#define NNZ      2400000
#define N_PROMPT 8
#define EPS_V    1e-8f

#define SCAN_B   1024
#define NBLK     ((NTOT + SCAN_B - 1) / SCAN_B)   // 147

// ---------------- scratch (device globals; no allocation allowed) -------------
__device__ int   g_count[NTOT];
__device__ int   g_cursor[NTOT];
__device__ int   g_rowptr[NTOT + 1];
__device__ int   g_bsum[256];
__device__ int2  g_perm[NNZ];                    // (col, val-as-int) packed 8B
__device__ float g_ego[(size_t)NTOT * EMB];
__device__ float g_xbuf[2 * (size_t)NTOT * EMB];
__device__ float g_egonorm[NTOT];

// ---------------- CSR build ---------------------------------------------------
__global__ void k_zero_counts() {
    int i = blockIdx.x * blockDim.x + threadIdx.x;
    if (i < NTOT) { g_count[i] = 0; g_cursor[i] = 0; }
}

__global__ void k_hist(const int* __restrict__ rows) {
    int e = blockIdx.x * blockDim.x + threadIdx.x;
    if (e < NNZ) atomicAdd(&g_count[rows[e]], 1);
}

__global__ void k_scan_block() {
    __shared__ int s[SCAN_B];
    int t = threadIdx.x;
    int i = blockIdx.x * SCAN_B + t;
    int v = (i < NTOT) ? g_count[i] : 0;
    s[t] = v;
    __syncthreads();
    for (int off = 1; off < SCAN_B; off <<= 1) {
        int u = (t >= off) ? s[t - off] : 0;
        __syncthreads();
        s[t] += u;
        __syncthreads();
    }
    if (i < NTOT) g_rowptr[i] = s[t] - v;        // exclusive within block
    if (t == SCAN_B - 1) g_bsum[blockIdx.x] = s[t];
}

__global__ void k_scan_sums(int nb) {
    __shared__ int s[256];
    int t = threadIdx.x;
    int v = (t < nb) ? g_bsum[t] : 0;
    s[t] = v;
    __syncthreads();
    for (int off = 1; off < 256; off <<= 1) {
        int u = (t >= off) ? s[t - off] : 0;
        __syncthreads();
        s[t] += u;
        __syncthreads();
    }
    g_bsum[t] = s[t] - v;                        // exclusive block offsets
}

__global__ void k_add_off() {
    int i = blockIdx.x * SCAN_B + threadIdx.x;
    if (i < NTOT) g_rowptr[i] += g_bsum[blockIdx.x];
    if (i == 0) g_rowptr[NTOT] = NNZ;
}

__global__ void k_scatter(const int* __restrict__ rows,
                          const int* __restrict__ cols,
                          const float* __restrict__ vals) {
    int e = blockIdx.x * blockDim.x + threadIdx.x;
    if (e >= NNZ) return;
    int r = rows[e];
    int pos = g_rowptr[r] + atomicAdd(&g_cursor[r], 1);
    g_perm[pos] = make_int2(cols[e], __float_as_int(vals[e]));
}

// ---------------- ego embedding ----------------------------------------------
__global__ void k_ego_user(const float4* __restrict__ uf,
                           const float* __restrict__ pe,
                           float4* __restrict__ dout) {
    __shared__ float sp[EMB];
    if (threadIdx.x < EMB) {
        float s = 0.f;
#pragma unroll
        for (int p = 0; p < N_PROMPT; ++p) s += pe[p * EMB + threadIdx.x];
        sp[threadIdx.x] = s;
    }
    __syncthreads();
    int idx = blockIdx.x * blockDim.x + threadIdx.x;     // over N_USER*16 float4s
    if (idx >= N_USER * (EMB / 4)) return;
    float4 v = uf[idx];
    int c4 = (idx & 15) * 4;
    v.x += sp[c4 + 0]; v.y += sp[c4 + 1]; v.z += sp[c4 + 2]; v.w += sp[c4 + 3];
    ((float4*)g_ego)[idx] = v;
    dout[idx] = v;
}

// warp-per-row GEMM: C = tanh(A[50000,384] @ W[384,64] + b), W in shared.
__global__ __launch_bounds__(256, 2)
void k_item_gemm(const float* __restrict__ A, const float* __restrict__ W,
                 const float* __restrict__ bias, float* __restrict__ dout) {
    extern __shared__ float smem[];
    float* s_w = smem;                 // FEAT*EMB, paired layout
    float* s_b = smem + FEAT * EMB;    // EMB
    for (int idx = threadIdx.x; idx < FEAT * EMB; idx += blockDim.x) {
        int k = idx >> 6, c = idx & 63;
        // pair col c and c+32 adjacently: float2 read per lane later
        s_w[k * EMB + ((c & 31) * 2 + (c >> 5))] = W[idx];
    }
    if (threadIdx.x < EMB) s_b[threadIdx.x] = bias[threadIdx.x];
    __syncthreads();

    int lane = threadIdx.x & 31;
    int warp = threadIdx.x >> 5;
    for (int row = blockIdx.x * 8 + warp; row < N_ITEM; row += gridDim.x * 8) {
        const float* Ar = A + (size_t)row * FEAT;
        float acc0 = 0.f, acc1 = 0.f;
#pragma unroll 4
        for (int kk = 0; kk < FEAT; kk += 4) {
            float4 a = *(const float4*)(Ar + kk);          // broadcast within warp
            const float* wp = s_w + kk * EMB + lane * 2;
            float2 w0 = *(const float2*)(wp);
            float2 w1 = *(const float2*)(wp + EMB);
            float2 w2 = *(const float2*)(wp + 2 * EMB);
            float2 w3 = *(const float2*)(wp + 3 * EMB);
            acc0 += a.x * w0.x; acc1 += a.x * w0.y;
            acc0 += a.y * w1.x; acc1 += a.y * w1.y;
            acc0 += a.z * w2.x; acc1 += a.z * w2.y;
            acc0 += a.w * w3.x; acc1 += a.w * w3.y;
        }
        float v0 = tanhf(acc0 + s_b[lane]);
        float v1 = tanhf(acc1 + s_b[lane + 32]);
        size_t o = (size_t)(N_USER + row) * EMB;
        g_ego[o + lane] = v0;      g_ego[o + 32 + lane] = v1;
        dout[o + lane]  = v0;      dout[o + 32 + lane]  = v1;
    }
}

__global__ void k_egonorm() {
    int warp = (blockIdx.x * blockDim.x + threadIdx.x) >> 5;
    int lane = threadIdx.x & 31;
    if (warp >= NTOT) return;
    size_t o = (size_t)warp * EMB;
    float e0 = g_ego[o + lane], e1 = g_ego[o + 32 + lane];
    float sq = e0 * e0 + e1 * e1;
#pragma unroll
    for (int s = 16; s; s >>= 1) sq += __shfl_xor_sync(~0u, sq, s);
    if (lane == 0) g_egonorm[warp] = sqrtf(sq);
}

// ---------------- fused SpMM + cosine reweight + layer accumulate -------------
// Warp per row; 2-wide edge unroll to raise load-level parallelism (two
// independent 256B row gathers in flight per iteration).
__global__ __launch_bounds__(256)
void k_spmm_fused(const float* __restrict__ xin, float* __restrict__ xout,
                  float* __restrict__ dout) {
    int row  = (blockIdx.x * blockDim.x + threadIdx.x) >> 5;
    int lane = threadIdx.x & 31;
    if (row >= NTOT) return;
    int beg = g_rowptr[row], end = g_rowptr[row + 1];
    float a0 = 0.f, a1 = 0.f;
    int e = beg;
    for (; e + 2 <= end; e += 2) {
        int2 ed0 = g_perm[e];
        int2 ed1 = g_perm[e + 1];
        const float* xr0 = xin + (size_t)ed0.x * EMB;
        const float* xr1 = xin + (size_t)ed1.x * EMB;
        float p00 = __ldg(xr0 + lane);
        float p01 = __ldg(xr0 + lane + 32);
        float p10 = __ldg(xr1 + lane);
        float p11 = __ldg(xr1 + lane + 32);
        float v0 = __int_as_float(ed0.y);
        float v1 = __int_as_float(ed1.y);
        a0 += v0 * p00; a1 += v0 * p01;
        a0 += v1 * p10; a1 += v1 * p11;
    }
    if (e < end) {
        int2 ed = g_perm[e];
        float v = __int_as_float(ed.y);
        const float* xr = xin + (size_t)ed.x * EMB;
        a0 += v * __ldg(xr + lane);
        a1 += v * __ldg(xr + lane + 32);
    }
    size_t o = (size_t)row * EMB;
    float e0 = g_ego[o + lane], e1 = g_ego[o + 32 + lane];
    float dot = a0 * e0 + a1 * e1;
    float sq  = a0 * a0 + a1 * a1;
#pragma unroll
    for (int s = 16; s; s >>= 1) {
        dot += __shfl_xor_sync(~0u, dot, s);
        sq  += __shfl_xor_sync(~0u, sq, s);
    }
    float w = dot / fmaxf(sqrtf(sq) * g_egonorm[row], EPS_V);
    a0 *= w; a1 *= w;
    xout[o + lane] = a0;             xout[o + 32 + lane] = a1;
    dout[o + lane] += a0;            dout[o + 32 + lane] += a1;
}

// ---------------- launch ------------------------------------------------------
extern "C" void kernel_launch(void* const* d_in, const int* in_sizes, int n_in,
                              void* d_out, int out_size) {
    const float* user_fea = (const float*)d_in[0];
    const float* item_fea = (const float*)d_in[1];
    const float* prompt   = (const float*)d_in[2];
    const float* mlp_w    = (const float*)d_in[3];
    const float* mlp_b    = (const float*)d_in[4];
    const int*   rows     = (const int*)d_in[5];
    const int*   cols     = (const int*)d_in[6];
    const float* vals     = (const float*)d_in[7];
    float* out = (float*)d_out;

    float *p_ego, *p_x;
    cudaGetSymbolAddress((void**)&p_ego, g_ego);
    cudaGetSymbolAddress((void**)&p_x, g_xbuf);
    float* p_x0 = p_x;
    float* p_x1 = p_x + (size_t)NTOT * EMB;

    const int gemm_smem = (FEAT * EMB + EMB) * (int)sizeof(float);  // 98560 B
    cudaFuncSetAttribute(k_item_gemm, cudaFuncAttributeMaxDynamicSharedMemorySize,
                         gemm_smem);

    // CSR build
    k_zero_counts<<<(NTOT + 255) / 256, 256>>>();
    k_hist<<<(NNZ + 255) / 256, 256>>>(rows);
    k_scan_block<<<NBLK, SCAN_B>>>();
    k_scan_sums<<<1, 256>>>(NBLK);
    k_add_off<<<NBLK, SCAN_B>>>();
    k_scatter<<<(NNZ + 255) / 256, 256>>>(rows, cols, vals);

    // ego embedding (also initializes acc = layer-0 term into d_out)
    k_ego_user<<<(N_USER * (EMB / 4) + 255) / 256, 256>>>(
        (const float4*)user_fea, prompt, (float4*)out);
    k_item_gemm<<<296, 256, gemm_smem>>>(item_fea, mlp_w, mlp_b, out);
    k_egonorm<<<(NTOT + 7) / 8, 256>>>();

    // 4 propagation layers, fused reweight + accumulate
    const int spmm_blocks = (NTOT * 32 + 255) / 256;   // warp per row
    k_spmm_fused<<<spmm_blocks, 256>>>(p_ego, p_x0, out);
    k_spmm_fused<<<spmm_blocks, 256>>>(p_x0, p_x1, out);
    k_spmm_fused<<<spmm_blocks, 256>>>(p_x1, p_x0, out);
    k_spmm_fused<<<spmm_blocks, 256>>>(p_x0, p_x1, out);
}

// round 3
// speedup vs baseline: 1.0956x; 1.0956x over previous
#include <cuda_runtime.h>
#include <cuda_fp16.h>
#include <math.h>

#define N_USER   100000
#define N_ITEM   50000
#define NTOT     150000
#define EMB      64
#define EMB2     32          // half2 / float2 elements per row
#define FEAT     384
#define NNZ      2400000
#define N_PROMPT 8
#define EPS_V    1e-8f

#define SCAN_B   1024
#define NBLK     ((NTOT + SCAN_B - 1) / SCAN_B)   // 147

// ---------------- scratch (device globals; no allocation allowed) -------------
__device__ int     g_count[NTOT];
__device__ int     g_cursor[NTOT];
__device__ int     g_rowptr[NTOT + 1];
__device__ int     g_bsum[256];
__device__ int2    g_perm[NNZ];                  // (col, val-as-int) packed 8B
__device__ float2  g_ego[(size_t)NTOT * EMB2];   // fp32 ego (final acc + norms)
__device__ __half2 g_ego_h[(size_t)NTOT * EMB2]; // fp16 ego (gather + dot)
__device__ __half2 g_xh[4][(size_t)NTOT * EMB2]; // per-layer propagated x (fp16)
__device__ float   g_egonorm[NTOT];

// ---------------- CSR build ---------------------------------------------------
__global__ void k_hist(const int* __restrict__ rows) {
    int e = blockIdx.x * blockDim.x + threadIdx.x;
    if (e < NNZ) atomicAdd(&g_count[rows[e]], 1);
}

__global__ void k_scan_block() {
    __shared__ int s[SCAN_B];
    int t = threadIdx.x;
    int i = blockIdx.x * SCAN_B + t;
    int v = (i < NTOT) ? g_count[i] : 0;
    s[t] = v;
    __syncthreads();
    for (int off = 1; off < SCAN_B; off <<= 1) {
        int u = (t >= off) ? s[t - off] : 0;
        __syncthreads();
        s[t] += u;
        __syncthreads();
    }
    if (i < NTOT) g_rowptr[i] = s[t] - v;        // exclusive within block
    if (t == SCAN_B - 1) g_bsum[blockIdx.x] = s[t];
}

__global__ void k_scan_sums(int nb) {
    __shared__ int s[256];
    int t = threadIdx.x;
    int v = (t < nb) ? g_bsum[t] : 0;
    s[t] = v;
    __syncthreads();
    for (int off = 1; off < 256; off <<= 1) {
        int u = (t >= off) ? s[t - off] : 0;
        __syncthreads();
        s[t] += u;
        __syncthreads();
    }
    g_bsum[t] = s[t] - v;                        // exclusive block offsets
}

__global__ void k_add_off() {
    int i = blockIdx.x * SCAN_B + threadIdx.x;
    if (i < NTOT) g_rowptr[i] += g_bsum[blockIdx.x];
    if (i == 0) g_rowptr[NTOT] = NNZ;
}

__global__ void k_scatter(const int* __restrict__ rows,
                          const int* __restrict__ cols,
                          const float* __restrict__ vals) {
    int e = blockIdx.x * blockDim.x + threadIdx.x;
    if (e >= NNZ) return;
    int r = rows[e];
    int pos = g_rowptr[r] + atomicAdd(&g_cursor[r], 1);
    g_perm[pos] = make_int2(cols[e], __float_as_int(vals[e]));
}

// ---------------- ego embedding (norm fused) ----------------------------------
// warp per user row: lane owns columns {2l, 2l+1}
__global__ __launch_bounds__(256)
void k_ego_user(const float2* __restrict__ uf, const float* __restrict__ pe) {
    __shared__ float sp[EMB];
    if (threadIdx.x < EMB) {
        float s = 0.f;
#pragma unroll
        for (int p = 0; p < N_PROMPT; ++p) s += pe[p * EMB + threadIdx.x];
        sp[threadIdx.x] = s;
    }
    __syncthreads();
    int row  = (blockIdx.x * blockDim.x + threadIdx.x) >> 5;
    int lane = threadIdx.x & 31;
    if (row >= N_USER) return;
    size_t o = (size_t)row * EMB2 + lane;
    float2 v = uf[o];
    v.x += sp[2 * lane];
    v.y += sp[2 * lane + 1];
    g_ego[o]   = v;
    g_ego_h[o] = __floats2half2_rn(v.x, v.y);
    float sq = v.x * v.x + v.y * v.y;
#pragma unroll
    for (int s = 16; s; s >>= 1) sq += __shfl_xor_sync(~0u, sq, s);
    if (lane == 0) g_egonorm[row] = sqrtf(sq);
}

// warp-per-row GEMM: tanh(A[50000,384] @ W[384,64] + b); W in shared, norm fused.
__global__ __launch_bounds__(256, 2)
void k_item_gemm(const float* __restrict__ A, const float* __restrict__ W,
                 const float* __restrict__ bias) {
    extern __shared__ float smem[];
    float* s_w = smem;                 // FEAT*EMB natural layout
    float* s_b = smem + FEAT * EMB;    // EMB
    for (int idx = threadIdx.x; idx < FEAT * EMB; idx += blockDim.x)
        s_w[idx] = W[idx];
    if (threadIdx.x < EMB) s_b[threadIdx.x] = bias[threadIdx.x];
    __syncthreads();

    int lane = threadIdx.x & 31;
    int warp = threadIdx.x >> 5;
    for (int row = blockIdx.x * 8 + warp; row < N_ITEM; row += gridDim.x * 8) {
        const float* Ar = A + (size_t)row * FEAT;
        float acc0 = 0.f, acc1 = 0.f;
#pragma unroll 4
        for (int kk = 0; kk < FEAT; kk += 4) {
            float4 a = *(const float4*)(Ar + kk);           // broadcast
            const float* wp = s_w + kk * EMB + 2 * lane;    // cols {2l,2l+1}
            float2 w0 = *(const float2*)(wp);
            float2 w1 = *(const float2*)(wp + EMB);
            float2 w2 = *(const float2*)(wp + 2 * EMB);
            float2 w3 = *(const float2*)(wp + 3 * EMB);
            acc0 += a.x * w0.x; acc1 += a.x * w0.y;
            acc0 += a.y * w1.x; acc1 += a.y * w1.y;
            acc0 += a.z * w2.x; acc1 += a.z * w2.y;
            acc0 += a.w * w3.x; acc1 += a.w * w3.y;
        }
        float v0 = tanhf(acc0 + s_b[2 * lane]);
        float v1 = tanhf(acc1 + s_b[2 * lane + 1]);
        size_t o = (size_t)(N_USER + row) * EMB2 + lane;
        g_ego[o]   = make_float2(v0, v1);
        g_ego_h[o] = __floats2half2_rn(v0, v1);
        float sq = v0 * v0 + v1 * v1;
#pragma unroll
        for (int s = 16; s; s >>= 1) sq += __shfl_xor_sync(~0u, sq, s);
        if (lane == 0) g_egonorm[N_USER + row] = sqrtf(sq);
    }
}

// ---------------- fused SpMM + cosine reweight (fp16 gather) ------------------
__global__ __launch_bounds__(256)
void k_spmm(const __half2* __restrict__ xin, __half2* __restrict__ xout) {
    int row  = (blockIdx.x * blockDim.x + threadIdx.x) >> 5;
    int lane = threadIdx.x & 31;
    if (row >= NTOT) return;
    int beg = g_rowptr[row], end = g_rowptr[row + 1];
    float a0 = 0.f, a1 = 0.f;
    int e = beg;
    for (; e + 4 <= end; e += 4) {                 // 4 independent gathers in flight
        int2 e0 = g_perm[e],     e1 = g_perm[e + 1];
        int2 e2 = g_perm[e + 2], e3 = g_perm[e + 3];
        float2 f0 = __half22float2(xin[(size_t)e0.x * EMB2 + lane]);
        float2 f1 = __half22float2(xin[(size_t)e1.x * EMB2 + lane]);
        float2 f2 = __half22float2(xin[(size_t)e2.x * EMB2 + lane]);
        float2 f3 = __half22float2(xin[(size_t)e3.x * EMB2 + lane]);
        float v0 = __int_as_float(e0.y), v1 = __int_as_float(e1.y);
        float v2 = __int_as_float(e2.y), v3 = __int_as_float(e3.y);
        a0 += v0 * f0.x; a1 += v0 * f0.y;
        a0 += v1 * f1.x; a1 += v1 * f1.y;
        a0 += v2 * f2.x; a1 += v2 * f2.y;
        a0 += v3 * f3.x; a1 += v3 * f3.y;
    }
    for (; e < end; ++e) {
        int2 ed = g_perm[e];
        float2 f = __half22float2(xin[(size_t)ed.x * EMB2 + lane]);
        float v = __int_as_float(ed.y);
        a0 += v * f.x; a1 += v * f.y;
    }
    size_t o = (size_t)row * EMB2 + lane;
    float2 ef = __half22float2(g_ego_h[o]);
    float dot = a0 * ef.x + a1 * ef.y;
    float sq  = a0 * a0 + a1 * a1;
#pragma unroll
    for (int s = 16; s; s >>= 1) {
        dot += __shfl_xor_sync(~0u, dot, s);
        sq  += __shfl_xor_sync(~0u, sq, s);
    }
    float w = dot / fmaxf(sqrtf(sq) * g_egonorm[row], EPS_V);
    xout[o] = __floats2half2_rn(a0 * w, a1 * w);
}

// ---------------- final accumulate: out = ego + x1 + x2 + x3 + x4 -------------
__global__ __launch_bounds__(256)
void k_final(float2* __restrict__ out) {
    size_t i = (size_t)blockIdx.x * blockDim.x + threadIdx.x;
    if (i >= (size_t)NTOT * EMB2) return;
    float2 a = g_ego[i];
#pragma unroll
    for (int l = 0; l < 4; ++l) {
        float2 x = __half22float2(g_xh[l][i]);
        a.x += x.x; a.y += x.y;
    }
    out[i] = a;
}

// ---------------- launch ------------------------------------------------------
extern "C" void kernel_launch(void* const* d_in, const int* in_sizes, int n_in,
                              void* d_out, int out_size) {
    const float* user_fea = (const float*)d_in[0];
    const float* item_fea = (const float*)d_in[1];
    const float* prompt   = (const float*)d_in[2];
    const float* mlp_w    = (const float*)d_in[3];
    const float* mlp_b    = (const float*)d_in[4];
    const int*   rows     = (const int*)d_in[5];
    const int*   cols     = (const int*)d_in[6];
    const float* vals     = (const float*)d_in[7];
    float2* out = (float2*)d_out;

    void *p_count, *p_cursor, *p_egoh, *p_xh;
    cudaGetSymbolAddress(&p_count, g_count);
    cudaGetSymbolAddress(&p_cursor, g_cursor);
    cudaGetSymbolAddress(&p_egoh, g_ego_h);
    cudaGetSymbolAddress(&p_xh, g_xh);
    __half2* xh = (__half2*)p_xh;
    const size_t XSTRIDE = (size_t)NTOT * EMB2;

    const int gemm_smem = (FEAT * EMB + EMB) * (int)sizeof(float);  // 98560 B
    cudaFuncSetAttribute(k_item_gemm, cudaFuncAttributeMaxDynamicSharedMemorySize,
                         gemm_smem);

    // CSR build
    cudaMemsetAsync(p_count, 0, NTOT * sizeof(int));
    cudaMemsetAsync(p_cursor, 0, NTOT * sizeof(int));
    k_hist<<<(NNZ + 255) / 256, 256>>>(rows);
    k_scan_block<<<NBLK, SCAN_B>>>();
    k_scan_sums<<<1, 256>>>(NBLK);
    k_add_off<<<NBLK, SCAN_B>>>();
    k_scatter<<<(NNZ + 255) / 256, 256>>>(rows, cols, vals);

    // ego embedding (+ fused norms)
    k_ego_user<<<(N_USER * 32 + 255) / 256, 256>>>((const float2*)user_fea, prompt);
    k_item_gemm<<<296, 256, gemm_smem>>>(item_fea, mlp_w, mlp_b);

    // 4 propagation layers (fp16 gather, fused cosine reweight)
    const int spmm_blocks = (NTOT * 32 + 255) / 256;   // warp per row
    k_spmm<<<spmm_blocks, 256>>>((const __half2*)p_egoh, xh);
    k_spmm<<<spmm_blocks, 256>>>(xh,               xh + XSTRIDE);
    k_spmm<<<spmm_blocks, 256>>>(xh + XSTRIDE,     xh + 2 * XSTRIDE);
    k_spmm<<<spmm_blocks, 256>>>(xh + 2 * XSTRIDE, xh + 3 * XSTRIDE);

    // out = ego + sum of layers
    k_final<<<(int)((XSTRIDE + 255) / 256), 256>>>(out);
}